// round 14
// baseline (speedup 1.0000x reference)
#include <cuda_runtime.h>
#include <cuda_fp16.h>
#include <cstdint>

#define BB 8
#define CC 256
#define NN 4096
#define NSPLIT 8

// Scratch (device globals — no allocation allowed)
__device__ __align__(128) half  g_Xh[BB * CC * NN];          // 16 MB  x in fp16
__device__ __align__(128) half  g_Ch[BB * CC * NN];          // 16 MB  cproj in fp16
__device__ __align__(128) half  g_Wqh[CC * CC];              // wq fp16
__device__ __align__(128) half  g_Wkvh[2 * CC * CC];         // wkv fp16
__device__ __align__(128) half  g_Qh[BB * CC * NN];          // 16 MB  Q logits (raw, fp16)
__device__ __align__(128) half  g_Kh[BB * CC * NN];          // 16 MB  K logits -> softmax(K)*4096
__device__ __align__(128) half  g_Vh[BB * CC * NN];          // 16 MB  V fp16
__device__ __align__(128) half  g_ctxh[NSPLIT][BB * CC * CC];// 8 MB   split-K partials fp16
__device__ __align__(128) half  g_Wch[BB * CC * CC];         // 1 MB   wo@ctx fp16

// ---------------------------------------------------------------------------
// helpers
// ---------------------------------------------------------------------------
__device__ __forceinline__ uint32_t smem_u32(const void* p) {
    uint32_t a;
    asm("{ .reg .u64 t; cvta.to.shared.u64 t, %1; cvt.u32.u64 %0, t; }" : "=r"(a) : "l"(p));
    return a;
}
__device__ __forceinline__ void cpa16(uint32_t dst, const void* src) {
    asm volatile("cp.async.cg.shared.global [%0], [%1], 16;" :: "r"(dst), "l"(src));
}
__device__ __forceinline__ void ldmx4(uint32_t* r, uint32_t addr) {
    asm volatile("ldmatrix.sync.aligned.m8n8.x4.shared.b16 {%0,%1,%2,%3}, [%4];"
                 : "=r"(r[0]), "=r"(r[1]), "=r"(r[2]), "=r"(r[3]) : "r"(addr));
}
__device__ __forceinline__ void ldmx4t(uint32_t* r, uint32_t addr) {
    asm volatile("ldmatrix.sync.aligned.m8n8.x4.trans.shared.b16 {%0,%1,%2,%3}, [%4];"
                 : "=r"(r[0]), "=r"(r[1]), "=r"(r[2]), "=r"(r[3]) : "r"(addr));
}
__device__ __forceinline__ void mma16816(float* c, const uint32_t* a, const uint32_t* b) {
    asm volatile(
        "mma.sync.aligned.m16n8k16.row.col.f32.f16.f16.f32 "
        "{%0,%1,%2,%3}, {%4,%5,%6,%7}, {%8,%9}, {%0,%1,%2,%3};"
        : "+f"(c[0]), "+f"(c[1]), "+f"(c[2]), "+f"(c[3])
        : "r"(a[0]), "r"(a[1]), "r"(a[2]), "r"(a[3]), "r"(b[0]), "r"(b[1]));
}
__device__ __forceinline__ uint4 pack8(float4 a, float4 b) {
    uint4 u;
    half2 h;
    h = __floats2half2_rn(a.x, a.y); u.x = *(const uint32_t*)&h;
    h = __floats2half2_rn(a.z, a.w); u.y = *(const uint32_t*)&h;
    h = __floats2half2_rn(b.x, b.y); u.z = *(const uint32_t*)&h;
    h = __floats2half2_rn(b.z, b.w); u.w = *(const uint32_t*)&h;
    return u;
}

// ---------------------------------------------------------------------------
// fp16 cp.async 3-stage GEMM core: C[128x128] += A[128xK] * B
// BKN=false: B [n][ldb] K-major (C = A * B^T);  BKN=true: B [k][ldb], n contig
// 256 threads, 8 warps (2x4), warp tile 64x32, m16n8k16, BK=32, NST=3.
// ---------------------------------------------------------------------------
template <bool BKN>
struct SmP {
    __align__(16) half A[3][128][40];
    __align__(16) half B[3][BKN ? 32 : 128][BKN ? 136 : 40];
};

template <bool BKN>
__device__ __forceinline__ void issue_stage(SmP<BKN>* s, int st,
                                            const half* __restrict__ Asrc, int lda,
                                            const half* __restrict__ Bsrc, int ldb, int t) {
#pragma unroll
    for (int r = 0; r < 2; r++) {
        const int idx = t + 256 * r;
        const int row = idx >> 2, seg = idx & 3;
        cpa16(smem_u32(&s->A[st][row][seg * 8]), Asrc + (size_t)row * lda + seg * 8);
    }
    if (BKN) {
#pragma unroll
        for (int r = 0; r < 2; r++) {
            const int idx = t + 256 * r;
            const int row = idx >> 4, seg = idx & 15;
            cpa16(smem_u32(&s->B[st][row][seg * 8]), Bsrc + (size_t)row * ldb + seg * 8);
        }
    } else {
#pragma unroll
        for (int r = 0; r < 2; r++) {
            const int idx = t + 256 * r;
            const int row = idx >> 2, seg = idx & 3;
            cpa16(smem_u32(&s->B[st][row][seg * 8]), Bsrc + (size_t)row * ldb + seg * 8);
        }
    }
}

template <bool BKN>
__device__ __forceinline__ void compute(SmP<BKN>* s, int buf, float acc[4][4][4],
                                        int wm, int wn, int lane) {
#pragma unroll
    for (int ks = 0; ks < 32; ks += 16) {
        uint32_t af[4][4];
#pragma unroll
        for (int mi = 0; mi < 4; mi++)
            ldmx4(af[mi],
                  smem_u32(&s->A[buf][wm + 16 * mi + (lane & 15)][ks + ((lane >> 4) << 3)]));
        uint32_t bf[4][2];
#pragma unroll
        for (int nj2 = 0; nj2 < 2; nj2++) {
            uint32_t r[4];
            if (BKN)
                ldmx4t(r, smem_u32(&s->B[buf][ks + (((lane >> 3) & 1) << 3) + (lane & 7)]
                                          [wn + nj2 * 16 + ((lane >> 4) << 3)]));
            else
                ldmx4(r, smem_u32(&s->B[buf][wn + nj2 * 16 + ((lane >> 4) << 3) + (lane & 7)]
                                         [ks + (((lane >> 3) & 1) << 3)]));
            bf[2 * nj2][0] = r[0]; bf[2 * nj2][1] = r[1];
            bf[2 * nj2 + 1][0] = r[2]; bf[2 * nj2 + 1][1] = r[3];
        }
#pragma unroll
        for (int mi = 0; mi < 4; mi++)
#pragma unroll
            for (int nj = 0; nj < 4; nj++)
                mma16816(acc[mi][nj], af[mi], bf[nj]);
    }
}

template <bool BKN>
__device__ __forceinline__ void gemm_run(SmP<BKN>* s, const half* __restrict__ A, int lda,
                                         const half* __restrict__ B, int ldb,
                                         int nIter, float acc[4][4][4]) {
    const int t = threadIdx.x, lane = t & 31, warp = t >> 5;
    const int wm = (warp >> 2) * 64, wn = (warp & 3) * 32;

#pragma unroll
    for (int st = 0; st < 2; st++) {
        if (st < nIter)
            issue_stage<BKN>(s, st, A + st * 32, lda,
                             BKN ? B + (size_t)st * 32 * ldb : B + st * 32, ldb, t);
        asm volatile("cp.async.commit_group;" ::: "memory");
    }
    int cur = 0;
    for (int it = 0; it < nIter; ++it) {
        asm volatile("cp.async.wait_group 1;" ::: "memory");
        __syncthreads();
        compute<BKN>(s, cur, acc, wm, wn, lane);
        const int nxt = it + 2;
        if (nxt < nIter) {
            int nst = cur + 2; if (nst >= 3) nst -= 3;
            issue_stage<BKN>(s, nst, A + nxt * 32, lda,
                             BKN ? B + (size_t)nxt * 32 * ldb : B + nxt * 32, ldb, t);
        }
        asm volatile("cp.async.commit_group;" ::: "memory");
        if (++cur == 3) cur = 0;
    }
}

// ---------------------------------------------------------------------------
// Kernel 0: convert x / cproj / wq / wkv -> fp16 in one launch.
// grid 8288: [0,4096) x, [4096,8192) cproj, [8192,8288) weights
// ---------------------------------------------------------------------------
__global__ __launch_bounds__(256) void conv_all(const float* __restrict__ x,
                                                const float* __restrict__ cp,
                                                const float* __restrict__ wq,
                                                const float* __restrict__ wkv)
{
    const int bid = blockIdx.x;
    if (bid < 8192) {
        const float* src = (bid < 4096) ? x : cp;
        half* dst = (bid < 4096) ? g_Xh : g_Ch;
        const int lb = bid & 4095;
        const size_t o = ((size_t)lb * 256 + threadIdx.x) * 8;
        float4 a = *(const float4*)(src + o);
        float4 b = *(const float4*)(src + o + 4);
        *(uint4*)(dst + o) = pack8(a, b);
    } else {
        const size_t o = (size_t)((bid - 8192) * 256 + threadIdx.x) * 8;
        const float* src;
        half* dst;
        size_t oo;
        if (o < CC * CC) { src = wq;  dst = g_Wqh;  oo = o; }
        else             { src = wkv; dst = g_Wkvh; oo = o - CC * CC; }
        float4 a = *(const float4*)(src + oo);
        float4 b = *(const float4*)(src + oo + 4);
        *(uint4*)(dst + oo) = pack8(a, b);
    }
}

// ---------------------------------------------------------------------------
// Kernel 1: Q/K logits + V, all fp16 outputs.
// y 0..1: Q -> g_Qh;  y 2..3: K -> g_Kh;  y 4..5: V -> g_Vh
// grid (32, 6, 8), 256 threads, dynamic smem
// ---------------------------------------------------------------------------
__global__ __launch_bounds__(256, 2) void gemm_qkv(
    const float* __restrict__ bq, const float* __restrict__ bkv)
{
    extern __shared__ __align__(16) char dyn[];
    SmP<true>* s = reinterpret_cast<SmP<true>*>(dyn);

    const int b = blockIdx.z;
    const int nbase = blockIdx.x * 128;
    const int yb = blockIdx.y;

    const half* W;
    const half* X;
    const float* bias;
    half* OutH;
    if (yb < 2) {
        W = g_Wqh + yb * 128 * CC; X = g_Xh; bias = bq + yb * 128;
        OutH = g_Qh + ((size_t)b * CC + yb * 128) * NN;
    } else {
        const int r = (yb - 2) * 128;
        W = g_Wkvh + r * CC; X = g_Ch; bias = bkv + r;
        if (r < CC) OutH = g_Kh + ((size_t)b * CC + r) * NN;
        else        OutH = g_Vh + ((size_t)b * CC + (r - CC)) * NN;
    }

    float acc[4][4][4] = {};
    gemm_run<true>(s, W, CC, X + (size_t)b * CC * NN + nbase, NN, CC / 32, acc);

    const int lane = threadIdx.x & 31, warp = threadIdx.x >> 5;
    const int wm = (warp >> 2) * 64, wn = (warp & 3) * 32;
    const int g = lane >> 2, tg = lane & 3;
#pragma unroll
    for (int i = 0; i < 4; i++) {
        const int r0 = wm + 16 * i + g;
        const float b0v = bias[r0], b1v = bias[r0 + 8];
#pragma unroll
        for (int j = 0; j < 4; j++) {
            const int col = nbase + wn + 8 * j + 2 * tg;
            *(__half2*)&OutH[(size_t)r0 * NN + col] =
                __floats2half2_rn(acc[i][j][0] + b0v, acc[i][j][1] + b0v);
            *(__half2*)&OutH[(size_t)(r0 + 8) * NN + col] =
                __floats2half2_rn(acc[i][j][2] + b1v, acc[i][j][3] + b1v);
        }
    }
}

// ---------------------------------------------------------------------------
// Kernel 2: softmax over N=4096 rows of g_Kh, in place, x4096. half2 I/O.
// grid 2048
// ---------------------------------------------------------------------------
__global__ __launch_bounds__(256) void softmax_k_kernel()
{
    __half2* p = (__half2*)(g_Kh + (size_t)blockIdx.x * NN);  // 2048 half2
    const int t = threadIdx.x;
    __shared__ float sh[8];

    float2 v[8];
    float m = -1e30f;
#pragma unroll
    for (int i = 0; i < 8; i++) {
        v[i] = __half22float2(p[t + 256 * i]);
        m = fmaxf(m, fmaxf(v[i].x, v[i].y));
    }
#pragma unroll
    for (int o = 16; o; o >>= 1) m = fmaxf(m, __shfl_xor_sync(0xffffffffu, m, o));
    if ((t & 31) == 0) sh[t >> 5] = m;
    __syncthreads();
    m = sh[0];
#pragma unroll
    for (int i = 1; i < 8; i++) m = fmaxf(m, sh[i]);

    float s = 0.f;
#pragma unroll
    for (int i = 0; i < 8; i++) {
        v[i].x = __expf(v[i].x - m);
        v[i].y = __expf(v[i].y - m);
        s += v[i].x + v[i].y;
    }
#pragma unroll
    for (int o = 16; o; o >>= 1) s += __shfl_xor_sync(0xffffffffu, s, o);
    __syncthreads();
    if ((t & 31) == 0) sh[t >> 5] = s;
    __syncthreads();
    s = 0.f;
#pragma unroll
    for (int i = 0; i < 8; i++) s += sh[i];

    const float inv = 4096.f / s;
#pragma unroll
    for (int i = 0; i < 8; i++)
        p[t + 256 * i] = __floats2half2_rn(v[i].x * inv, v[i].y * inv);
}

// ---------------------------------------------------------------------------
// Kernel 3: ctx partial (x4096, fp16) = k_s-tile @ V-tile^T over split n-range.
// grid (2, 2, 64): z = b*8 + split, K=512 per split.  dynamic smem
// ---------------------------------------------------------------------------
__global__ __launch_bounds__(256, 2) void gemm_ctx()
{
    extern __shared__ __align__(16) char dyn[];
    SmP<false>* s = reinterpret_cast<SmP<false>*>(dyn);

    const int split = blockIdx.z & 7;
    const int b = blockIdx.z >> 3;
    const int mbase = blockIdx.y * 128;
    const int nbase = blockIdx.x * 128;
    const int k0 = split * 512;

    float acc[4][4][4] = {};
    gemm_run<false>(s, g_Kh + ((size_t)b * CC + mbase) * NN + k0, NN,
                    g_Vh + ((size_t)b * CC + nbase) * NN + k0, NN, 512 / 32, acc);

    half* Out = g_ctxh[split] + ((size_t)b * CC + mbase) * CC + nbase;
    const int lane = threadIdx.x & 31, warp = threadIdx.x >> 5;
    const int wm = (warp >> 2) * 64, wn = (warp & 3) * 32;
    const int g = lane >> 2, tg = lane & 3;
#pragma unroll
    for (int i = 0; i < 4; i++) {
        const int r0 = wm + 16 * i + g;
#pragma unroll
        for (int j = 0; j < 4; j++) {
            const int col = wn + 8 * j + 2 * tg;
            *(__half2*)&Out[(size_t)r0 * CC + col] =
                __floats2half2_rn(acc[i][j][0], acc[i][j][1]);
            *(__half2*)&Out[(size_t)(r0 + 8) * CC + col] =
                __floats2half2_rn(acc[i][j][2], acc[i][j][3]);
        }
    }
}

// ---------------------------------------------------------------------------
// Kernel 4: Wc[b] = wo @ (sum of 8 fp16 ctx partials)/4096 -> fp16. SIMT.
// grid (4, 4, 8), 256 threads, 64x64 tiles.
// ---------------------------------------------------------------------------
__global__ __launch_bounds__(256) void gemm_wc(const float* __restrict__ wo)
{
    __shared__ __align__(16) float As[16][68];
    __shared__ __align__(16) float Bs[16][68];

    const int b = blockIdx.z;
    const int mbase = blockIdx.y * 64;
    const int nbase = blockIdx.x * 64;
    const float* Aptr = wo + mbase * CC;
    const size_t boff = (size_t)b * CC * CC + nbase;

    const int t = threadIdx.x;
    const int tx = t & 15, ty = t >> 4;
    const int arow = t >> 4, acol = t & 15;
    const int bcol = t & 63, brow = t >> 6;

    float acc[4][4] = {};
    for (int k0 = 0; k0 < CC; k0 += 16) {
#pragma unroll
        for (int r = 0; r < 4; r++)
            As[acol][arow + 16 * r] = Aptr[(arow + 16 * r) * CC + k0 + acol];
#pragma unroll
        for (int r = 0; r < 4; r++) {
            const size_t kr = boff + (size_t)(k0 + brow + 4 * r) * CC + bcol;
            float s = 0.f;
#pragma unroll
            for (int p = 0; p < NSPLIT; p++) s += __half2float(g_ctxh[p][kr]);
            Bs[brow + 4 * r][bcol] = s * (1.f / 4096.f);
        }
        __syncthreads();
#pragma unroll
        for (int kk = 0; kk < 16; kk++) {
            float4 a4 = *(const float4*)&As[kk][ty * 4];
            float4 b4 = *(const float4*)&Bs[kk][tx * 4];
            float av[4] = {a4.x, a4.y, a4.z, a4.w};
            float bw[4] = {b4.x, b4.y, b4.z, b4.w};
#pragma unroll
            for (int i = 0; i < 4; i++)
#pragma unroll
                for (int j = 0; j < 4; j++) acc[i][j] += av[i] * bw[j];
        }
        __syncthreads();
    }

    half* Out = g_Wch + ((size_t)b * CC + mbase) * CC + nbase;
#pragma unroll
    for (int i = 0; i < 4; i++) {
        *(__half2*)&Out[(ty * 4 + i) * CC + tx * 4]     = __floats2half2_rn(acc[i][0], acc[i][1]);
        *(__half2*)&Out[(ty * 4 + i) * CC + tx * 4 + 2] = __floats2half2_rn(acc[i][2], acc[i][3]);
    }
}

// ---------------------------------------------------------------------------
// Kernel 5 (fused): out[b] = Wc[b] @ softmax_d(0.25*Qlogits) + bo.
// B tile (q logits, [k=256][n=128]) fully resident in smem; softmax over each
// 64-row channel group in-place; A (Wc) pipelined.  grid (32, 2, 8), dyn smem
// ---------------------------------------------------------------------------
struct SmOut {
    __align__(16) half A[3][128][40];   // 30 KB
    __align__(16) half B[256][136];     // 68 KB (same 136 pitch as staged path)
};

__global__ __launch_bounds__(256, 2) void gemm_out(const float* __restrict__ bo,
                                                   float* __restrict__ out)
{
    extern __shared__ __align__(16) char dyn[];
    SmOut* s = reinterpret_cast<SmOut*>(dyn);

    const int t = threadIdx.x, lane = t & 31, warp = t >> 5;
    const int wm = (warp >> 2) * 64, wn = (warp & 3) * 32;
    const int b = blockIdx.z;
    const int mbase = blockIdx.y * 128;
    const int nbase = blockIdx.x * 128;

    const half* Asrc = g_Wch + (size_t)b * CC * CC + mbase * CC;     // [m][k], lda=CC
    const half* Bsrc = g_Qh + (size_t)b * CC * NN + nbase;           // [k][n], ldb=NN

    // Issue whole B tile (256x128 halves = 64KB = 4096 16B chunks)
#pragma unroll
    for (int r = 0; r < 16; r++) {
        const int idx = t + 256 * r;
        const int row = idx >> 4, seg = idx & 15;
        cpa16(smem_u32(&s->B[row][seg * 8]), Bsrc + (size_t)row * NN + seg * 8);
    }
    // Issue A stages 0,1 (each 128x32 = 512 chunks)
#pragma unroll
    for (int st = 0; st < 2; st++) {
#pragma unroll
        for (int r = 0; r < 2; r++) {
            const int idx = t + 256 * r;
            const int row = idx >> 2, seg = idx & 3;
            cpa16(smem_u32(&s->A[st][row][seg * 8]),
                  Asrc + (size_t)row * CC + st * 32 + seg * 8);
        }
        asm volatile("cp.async.commit_group;" ::: "memory");
    }
    asm volatile("cp.async.wait_group 0;" ::: "memory");
    __syncthreads();

    // In-smem softmax over d=64 groups: thread -> (col = t&127, khalf = t>>7)
    {
        const int col = t & 127;
        const int kbase = (t >> 7) * 128;  // two 64-groups per thread
#pragma unroll
        for (int gidx = 0; gidx < 2; gidx++) {
            const int k0 = kbase + gidx * 64;
            float m = -1e30f;
#pragma unroll
            for (int d = 0; d < 64; d++)
                m = fmaxf(m, __half2float(s->B[k0 + d][col]));
            float sum = 0.f;
#pragma unroll
            for (int d = 0; d < 64; d++)
                sum += __expf((__half2float(s->B[k0 + d][col]) - m) * 0.25f);
            const float inv = 1.f / sum;
#pragma unroll
            for (int d = 0; d < 64; d++)
                s->B[k0 + d][col] =
                    __float2half(__expf((__half2float(s->B[k0 + d][col]) - m) * 0.25f) * inv);
        }
    }
    __syncthreads();

    // Mainloop: A pipelined (3 stages), B resident.
    float acc[4][4][4] = {};
    int cur = 0;
    for (int it = 0; it < 8; ++it) {
        if (it > 0) {
            asm volatile("cp.async.wait_group 1;" ::: "memory");
            __syncthreads();
        }
        const int kch = it * 32;
#pragma unroll
        for (int ks = 0; ks < 32; ks += 16) {
            uint32_t af[4][4];
#pragma unroll
            for (int mi = 0; mi < 4; mi++)
                ldmx4(af[mi], smem_u32(&s->A[cur][wm + 16 * mi + (lane & 15)]
                                            [ks + ((lane >> 4) << 3)]));
            uint32_t bf[4][2];
#pragma unroll
            for (int nj2 = 0; nj2 < 2; nj2++) {
                uint32_t r[4];
                ldmx4t(r, smem_u32(&s->B[kch + ks + (((lane >> 3) & 1) << 3) + (lane & 7)]
                                        [wn + nj2 * 16 + ((lane >> 4) << 3)]));
                bf[2 * nj2][0] = r[0]; bf[2 * nj2][1] = r[1];
                bf[2 * nj2 + 1][0] = r[2]; bf[2 * nj2 + 1][1] = r[3];
            }
#pragma unroll
            for (int mi = 0; mi < 4; mi++)
#pragma unroll
                for (int nj = 0; nj < 4; nj++)
                    mma16816(acc[mi][nj], af[mi], bf[nj]);
        }
        const int nxt = it + 2;
        if (nxt < 8) {
            int nst = cur + 2; if (nst >= 3) nst -= 3;
#pragma unroll
            for (int r = 0; r < 2; r++) {
                const int idx = t + 256 * r;
                const int row = idx >> 2, seg = idx & 3;
                cpa16(smem_u32(&s->A[nst][row][seg * 8]),
                      Asrc + (size_t)row * CC + nxt * 32 + seg * 8);
            }
        }
        asm volatile("cp.async.commit_group;" ::: "memory");
        if (++cur == 3) cur = 0;
    }

    float* OutB = out + ((size_t)b * CC + mbase) * NN + nbase;
    const int g = lane >> 2, tg = lane & 3;
#pragma unroll
    for (int i = 0; i < 4; i++) {
        const int r0 = wm + 16 * i + g;
        const float b0v = bo[mbase + r0], b1v = bo[mbase + r0 + 8];
#pragma unroll
        for (int j = 0; j < 4; j++) {
            const int col = wn + 8 * j + 2 * tg;
            *(float2*)&OutB[(size_t)r0 * NN + col] =
                make_float2(acc[i][j][0] + b0v, acc[i][j][1] + b0v);
            *(float2*)&OutB[(size_t)(r0 + 8) * NN + col] =
                make_float2(acc[i][j][2] + b1v, acc[i][j][3] + b1v);
        }
    }
}

// ---------------------------------------------------------------------------
extern "C" void kernel_launch(void* const* d_in, const int* in_sizes, int n_in,
                              void* d_out, int out_size)
{
    const float* x    = (const float*)d_in[0];
    const float* cp   = (const float*)d_in[1];
    const float* wq   = (const float*)d_in[2];
    const float* bq   = (const float*)d_in[3];
    const float* wkv  = (const float*)d_in[4];
    const float* bkv  = (const float*)d_in[5];
    const float* wo   = (const float*)d_in[6];
    const float* bo   = (const float*)d_in[7];
    float* out = (float*)d_out;

    const int smA = (int)sizeof(SmP<true>);   // ~56.8 KB
    const int smC = (int)sizeof(SmP<false>);  // ~61.4 KB
    const int smO = (int)sizeof(SmOut);       // ~98 KB
    cudaFuncSetAttribute(gemm_qkv, cudaFuncAttributeMaxDynamicSharedMemorySize, smA);
    cudaFuncSetAttribute(gemm_ctx, cudaFuncAttributeMaxDynamicSharedMemorySize, smC);
    cudaFuncSetAttribute(gemm_out, cudaFuncAttributeMaxDynamicSharedMemorySize, smO);

    conv_all<<<8288, 256>>>(x, cp, wq, wkv);
    gemm_qkv<<<dim3(32, 6, 8), 256, smA>>>(bq, bkv);
    softmax_k_kernel<<<2048, 256>>>();
    gemm_ctx<<<dim3(2, 2, 64), 256, smC>>>();
    gemm_wc<<<dim3(4, 4, 8), 256>>>(wo);
    gemm_out<<<dim3(32, 2, 8), 256, smO>>>(bo, out);
}

// round 15
// speedup vs baseline: 1.0315x; 1.0315x over previous
#include <cuda_runtime.h>
#include <cuda_fp16.h>
#include <cstdint>

#define BB 8
#define CC 256
#define NN 4096
#define NSPLIT 8

// Scratch (device globals — no allocation allowed)
__device__ __align__(128) half  g_Xh[BB * CC * NN];          // 16 MB  x in fp16
__device__ __align__(128) half  g_Ch[BB * CC * NN];          // 16 MB  cproj in fp16
__device__ __align__(128) half  g_Wqh[CC * CC];              // wq fp16
__device__ __align__(128) half  g_Wkvh[2 * CC * CC];         // wkv fp16
__device__ __align__(128) half  g_Qh[BB * CC * NN];          // 16 MB  Q logits -> softmax(Q)*64
__device__ __align__(128) half  g_Kh[BB * CC * NN];          // 16 MB  exp(K logits), unnormalized
__device__ __align__(128) half  g_Vh[BB * CC * NN];          // 16 MB  V fp16
__device__ __align__(128) half  g_ctxh[NSPLIT][BB * CC * CC];// 8 MB   split-K partials fp16
__device__ __align__(128) half  g_Wch[BB * CC * CC];         // 1 MB   wo@ctx fp16
__device__ __align__(128) float g_invS[BB * CC];             // 8 KB   1/rowsum of exp(K)

// ---------------------------------------------------------------------------
// helpers
// ---------------------------------------------------------------------------
__device__ __forceinline__ uint32_t smem_u32(const void* p) {
    uint32_t a;
    asm("{ .reg .u64 t; cvta.to.shared.u64 t, %1; cvt.u32.u64 %0, t; }" : "=r"(a) : "l"(p));
    return a;
}
__device__ __forceinline__ void cpa16(uint32_t dst, const void* src) {
    asm volatile("cp.async.cg.shared.global [%0], [%1], 16;" :: "r"(dst), "l"(src));
}
__device__ __forceinline__ void ldmx4(uint32_t* r, uint32_t addr) {
    asm volatile("ldmatrix.sync.aligned.m8n8.x4.shared.b16 {%0,%1,%2,%3}, [%4];"
                 : "=r"(r[0]), "=r"(r[1]), "=r"(r[2]), "=r"(r[3]) : "r"(addr));
}
__device__ __forceinline__ void ldmx4t(uint32_t* r, uint32_t addr) {
    asm volatile("ldmatrix.sync.aligned.m8n8.x4.trans.shared.b16 {%0,%1,%2,%3}, [%4];"
                 : "=r"(r[0]), "=r"(r[1]), "=r"(r[2]), "=r"(r[3]) : "r"(addr));
}
__device__ __forceinline__ void mma16816(float* c, const uint32_t* a, const uint32_t* b) {
    asm volatile(
        "mma.sync.aligned.m16n8k16.row.col.f32.f16.f16.f32 "
        "{%0,%1,%2,%3}, {%4,%5,%6,%7}, {%8,%9}, {%0,%1,%2,%3};"
        : "+f"(c[0]), "+f"(c[1]), "+f"(c[2]), "+f"(c[3])
        : "r"(a[0]), "r"(a[1]), "r"(a[2]), "r"(a[3]), "r"(b[0]), "r"(b[1]));
}
__device__ __forceinline__ uint4 pack8(float4 a, float4 b) {
    uint4 u;
    half2 h;
    h = __floats2half2_rn(a.x, a.y); u.x = *(const uint32_t*)&h;
    h = __floats2half2_rn(a.z, a.w); u.y = *(const uint32_t*)&h;
    h = __floats2half2_rn(b.x, b.y); u.z = *(const uint32_t*)&h;
    h = __floats2half2_rn(b.z, b.w); u.w = *(const uint32_t*)&h;
    return u;
}

// ---------------------------------------------------------------------------
// fp16 cp.async 3-stage GEMM core: C[128x128] += A[128xK] * B
// BKN=false: B [n][ldb] K-major (C = A * B^T);  BKN=true: B [k][ldb], n contig
// 256 threads, 8 warps (2x4), warp tile 64x32, m16n8k16, BK=32, NST=3.
// ---------------------------------------------------------------------------
template <bool BKN>
struct SmP {
    __align__(16) half A[3][128][40];
    __align__(16) half B[3][BKN ? 32 : 128][BKN ? 136 : 40];
};

template <bool BKN>
__device__ __forceinline__ void issue_stage(SmP<BKN>* s, int st,
                                            const half* __restrict__ Asrc, int lda,
                                            const half* __restrict__ Bsrc, int ldb, int t) {
#pragma unroll
    for (int r = 0; r < 2; r++) {
        const int idx = t + 256 * r;
        const int row = idx >> 2, seg = idx & 3;
        cpa16(smem_u32(&s->A[st][row][seg * 8]), Asrc + (size_t)row * lda + seg * 8);
    }
    if (BKN) {
#pragma unroll
        for (int r = 0; r < 2; r++) {
            const int idx = t + 256 * r;
            const int row = idx >> 4, seg = idx & 15;
            cpa16(smem_u32(&s->B[st][row][seg * 8]), Bsrc + (size_t)row * ldb + seg * 8);
        }
    } else {
#pragma unroll
        for (int r = 0; r < 2; r++) {
            const int idx = t + 256 * r;
            const int row = idx >> 2, seg = idx & 3;
            cpa16(smem_u32(&s->B[st][row][seg * 8]), Bsrc + (size_t)row * ldb + seg * 8);
        }
    }
}

template <bool BKN>
__device__ __forceinline__ void compute(SmP<BKN>* s, int buf, float acc[4][4][4],
                                        int wm, int wn, int lane) {
#pragma unroll
    for (int ks = 0; ks < 32; ks += 16) {
        uint32_t af[4][4];
#pragma unroll
        for (int mi = 0; mi < 4; mi++)
            ldmx4(af[mi],
                  smem_u32(&s->A[buf][wm + 16 * mi + (lane & 15)][ks + ((lane >> 4) << 3)]));
        uint32_t bf[4][2];
#pragma unroll
        for (int nj2 = 0; nj2 < 2; nj2++) {
            uint32_t r[4];
            if (BKN)
                ldmx4t(r, smem_u32(&s->B[buf][ks + (((lane >> 3) & 1) << 3) + (lane & 7)]
                                          [wn + nj2 * 16 + ((lane >> 4) << 3)]));
            else
                ldmx4(r, smem_u32(&s->B[buf][wn + nj2 * 16 + ((lane >> 4) << 3) + (lane & 7)]
                                         [ks + (((lane >> 3) & 1) << 3)]));
            bf[2 * nj2][0] = r[0]; bf[2 * nj2][1] = r[1];
            bf[2 * nj2 + 1][0] = r[2]; bf[2 * nj2 + 1][1] = r[3];
        }
#pragma unroll
        for (int mi = 0; mi < 4; mi++)
#pragma unroll
            for (int nj = 0; nj < 4; nj++)
                mma16816(acc[mi][nj], af[mi], bf[nj]);
    }
}

template <bool BKN>
__device__ __forceinline__ void gemm_run(SmP<BKN>* s, const half* __restrict__ A, int lda,
                                         const half* __restrict__ B, int ldb,
                                         int nIter, float acc[4][4][4]) {
    const int t = threadIdx.x, lane = t & 31, warp = t >> 5;
    const int wm = (warp >> 2) * 64, wn = (warp & 3) * 32;

#pragma unroll
    for (int st = 0; st < 2; st++) {
        if (st < nIter)
            issue_stage<BKN>(s, st, A + st * 32, lda,
                             BKN ? B + (size_t)st * 32 * ldb : B + st * 32, ldb, t);
        asm volatile("cp.async.commit_group;" ::: "memory");
    }
    int cur = 0;
    for (int it = 0; it < nIter; ++it) {
        asm volatile("cp.async.wait_group 1;" ::: "memory");
        __syncthreads();
        compute<BKN>(s, cur, acc, wm, wn, lane);
        const int nxt = it + 2;
        if (nxt < nIter) {
            int nst = cur + 2; if (nst >= 3) nst -= 3;
            issue_stage<BKN>(s, nst, A + nxt * 32, lda,
                             BKN ? B + (size_t)nxt * 32 * ldb : B + nxt * 32, ldb, t);
        }
        asm volatile("cp.async.commit_group;" ::: "memory");
        if (++cur == 3) cur = 0;
    }
}

// ---------------------------------------------------------------------------
// Kernel 0: convert x / cproj / wq / wkv -> fp16 in one launch.
// grid 8288: [0,4096) x, [4096,8192) cproj, [8192,8288) weights
// ---------------------------------------------------------------------------
__global__ __launch_bounds__(256) void conv_all(const float* __restrict__ x,
                                                const float* __restrict__ cp,
                                                const float* __restrict__ wq,
                                                const float* __restrict__ wkv)
{
    const int bid = blockIdx.x;
    if (bid < 8192) {
        const float* src = (bid < 4096) ? x : cp;
        half* dst = (bid < 4096) ? g_Xh : g_Ch;
        const int lb = bid & 4095;
        const size_t o = ((size_t)lb * 256 + threadIdx.x) * 8;
        float4 a = *(const float4*)(src + o);
        float4 b = *(const float4*)(src + o + 4);
        *(uint4*)(dst + o) = pack8(a, b);
    } else {
        const size_t o = (size_t)((bid - 8192) * 256 + threadIdx.x) * 8;
        const float* src;
        half* dst;
        size_t oo;
        if (o < CC * CC) { src = wq;  dst = g_Wqh;  oo = o; }
        else             { src = wkv; dst = g_Wkvh; oo = o - CC * CC; }
        float4 a = *(const float4*)(src + oo);
        float4 b = *(const float4*)(src + oo + 4);
        *(uint4*)(dst + oo) = pack8(a, b);
    }
}

// ---------------------------------------------------------------------------
// Kernel 1: Q/K logits + V, all fp16 outputs.
// y 0..1: Q logits -> g_Qh;  y 2..3: exp(K logits) -> g_Kh;  y 4..5: V -> g_Vh
// grid (32, 6, 8), 256 threads, dynamic smem
// ---------------------------------------------------------------------------
__global__ __launch_bounds__(256, 2) void gemm_qkv(
    const float* __restrict__ bq, const float* __restrict__ bkv)
{
    extern __shared__ __align__(16) char dyn[];
    SmP<true>* s = reinterpret_cast<SmP<true>*>(dyn);

    const int b = blockIdx.z;
    const int nbase = blockIdx.x * 128;
    const int yb = blockIdx.y;

    const half* W;
    const half* X;
    const float* bias;
    half* OutH;
    int kexp = 0;
    if (yb < 2) {
        W = g_Wqh + yb * 128 * CC; X = g_Xh; bias = bq + yb * 128;
        OutH = g_Qh + ((size_t)b * CC + yb * 128) * NN;
    } else {
        const int r = (yb - 2) * 128;
        W = g_Wkvh + r * CC; X = g_Ch; bias = bkv + r;
        if (r < CC) { OutH = g_Kh + ((size_t)b * CC + r) * NN; kexp = 1; }
        else        OutH = g_Vh + ((size_t)b * CC + (r - CC)) * NN;
    }

    float acc[4][4][4] = {};
    gemm_run<true>(s, W, CC, X + (size_t)b * CC * NN + nbase, NN, CC / 32, acc);

    const int lane = threadIdx.x & 31, warp = threadIdx.x >> 5;
    const int wm = (warp >> 2) * 64, wn = (warp & 3) * 32;
    const int g = lane >> 2, tg = lane & 3;
#pragma unroll
    for (int i = 0; i < 4; i++) {
        const int r0 = wm + 16 * i + g;
        const float b0v = bias[r0], b1v = bias[r0 + 8];
#pragma unroll
        for (int j = 0; j < 4; j++) {
            const int col = nbase + wn + 8 * j + 2 * tg;
            float v0 = acc[i][j][0] + b0v, v1 = acc[i][j][1] + b0v;
            float v2 = acc[i][j][2] + b1v, v3 = acc[i][j][3] + b1v;
            if (kexp) {
                v0 = __expf(fminf(v0, 10.f)); v1 = __expf(fminf(v1, 10.f));
                v2 = __expf(fminf(v2, 10.f)); v3 = __expf(fminf(v3, 10.f));
            }
            *(__half2*)&OutH[(size_t)r0 * NN + col] = __floats2half2_rn(v0, v1);
            *(__half2*)&OutH[(size_t)(r0 + 8) * NN + col] = __floats2half2_rn(v2, v3);
        }
    }
}

// ---------------------------------------------------------------------------
// Kernel 2: merged pass.
// blocks [0,2048): rowsum of exp(K) row -> g_invS (read-only over g_Kh)
// blocks [2048,2560): softmax over d=64 of 0.25*Q on g_Qh in place, x64
// ---------------------------------------------------------------------------
__global__ __launch_bounds__(256) void softmax_all()
{
    const int bid = blockIdx.x;
    const int t = threadIdx.x;
    if (bid < 2048) {
        const __half2* p = (const __half2*)(g_Kh + (size_t)bid * NN);  // 2048 half2
        __shared__ float sh[8];

        float s = 0.f;
#pragma unroll
        for (int i = 0; i < 8; i++) {
            float2 f = __half22float2(p[t + 256 * i]);
            s += f.x + f.y;
        }
#pragma unroll
        for (int o = 16; o; o >>= 1) s += __shfl_xor_sync(0xffffffffu, s, o);
        if ((t & 31) == 0) sh[t >> 5] = s;
        __syncthreads();
        if (t == 0) {
            float tot = 0.f;
#pragma unroll
            for (int i = 0; i < 8; i++) tot += sh[i];
            g_invS[bid] = 1.f / tot;
        }
    } else {
        const int idx = (bid - 2048) * 256 + t;
        const int n = idx & (NN - 1);
        const int bh = idx >> 12;
        half* base = g_Qh + (size_t)bh * 64 * NN + n;

        float v[64];
        float m = -1e30f;
#pragma unroll
        for (int d = 0; d < 64; d++) { v[d] = __half2float(base[d * NN]); m = fmaxf(m, v[d]); }
        float s = 0.f;
#pragma unroll
        for (int d = 0; d < 64; d++) { v[d] = __expf((v[d] - m) * 0.25f); s += v[d]; }
        const float inv = 64.f / s;
#pragma unroll
        for (int d = 0; d < 64; d++) base[d * NN] = __float2half(v[d] * inv);
    }
}

// ---------------------------------------------------------------------------
// Kernel 3: ctx partial (fp16) = exp(K)-tile @ V-tile^T over split n-range.
// grid (2, 2, 64): z = b*8 + split, K=512 per split.  dynamic smem
// ---------------------------------------------------------------------------
__global__ __launch_bounds__(256, 2) void gemm_ctx()
{
    extern __shared__ __align__(16) char dyn[];
    SmP<false>* s = reinterpret_cast<SmP<false>*>(dyn);

    const int split = blockIdx.z & 7;
    const int b = blockIdx.z >> 3;
    const int mbase = blockIdx.y * 128;
    const int nbase = blockIdx.x * 128;
    const int k0 = split * 512;

    float acc[4][4][4] = {};
    gemm_run<false>(s, g_Kh + ((size_t)b * CC + mbase) * NN + k0, NN,
                    g_Vh + ((size_t)b * CC + nbase) * NN + k0, NN, 512 / 32, acc);

    half* Out = g_ctxh[split] + ((size_t)b * CC + mbase) * CC + nbase;
    const int lane = threadIdx.x & 31, warp = threadIdx.x >> 5;
    const int wm = (warp >> 2) * 64, wn = (warp & 3) * 32;
    const int g = lane >> 2, tg = lane & 3;
#pragma unroll
    for (int i = 0; i < 4; i++) {
        const int r0 = wm + 16 * i + g;
#pragma unroll
        for (int j = 0; j < 4; j++) {
            const int col = wn + 8 * j + 2 * tg;
            *(__half2*)&Out[(size_t)r0 * CC + col] =
                __floats2half2_rn(acc[i][j][0], acc[i][j][1]);
            *(__half2*)&Out[(size_t)(r0 + 8) * CC + col] =
                __floats2half2_rn(acc[i][j][2], acc[i][j][3]);
        }
    }
}

// ---------------------------------------------------------------------------
// Kernel 4: Wc[b] = wo @ (invS-normalized sum of 8 ctx partials) -> fp16. SIMT.
// grid (4, 4, 8), 256 threads, 64x64 tiles.
// ---------------------------------------------------------------------------
__global__ __launch_bounds__(256) void gemm_wc(const float* __restrict__ wo)
{
    __shared__ __align__(16) float As[16][68];
    __shared__ __align__(16) float Bs[16][68];

    const int b = blockIdx.z;
    const int mbase = blockIdx.y * 64;
    const int nbase = blockIdx.x * 64;
    const float* Aptr = wo + mbase * CC;
    const size_t boff = (size_t)b * CC * CC + nbase;
    const float* invS = g_invS + b * CC;

    const int t = threadIdx.x;
    const int tx = t & 15, ty = t >> 4;
    const int arow = t >> 4, acol = t & 15;
    const int bcol = t & 63, brow = t >> 6;

    float acc[4][4] = {};
    for (int k0 = 0; k0 < CC; k0 += 16) {
#pragma unroll
        for (int r = 0; r < 4; r++)
            As[acol][arow + 16 * r] = Aptr[(arow + 16 * r) * CC + k0 + acol];
#pragma unroll
        for (int r = 0; r < 4; r++) {
            const int krow = k0 + brow + 4 * r;
            const size_t kr = boff + (size_t)krow * CC + bcol;
            float s = 0.f;
#pragma unroll
            for (int p = 0; p < NSPLIT; p++) s += __half2float(g_ctxh[p][kr]);
            Bs[brow + 4 * r][bcol] = s * invS[krow];
        }
        __syncthreads();
#pragma unroll
        for (int kk = 0; kk < 16; kk++) {
            float4 a4 = *(const float4*)&As[kk][ty * 4];
            float4 b4 = *(const float4*)&Bs[kk][tx * 4];
            float av[4] = {a4.x, a4.y, a4.z, a4.w};
            float bw[4] = {b4.x, b4.y, b4.z, b4.w};
#pragma unroll
            for (int i = 0; i < 4; i++)
#pragma unroll
                for (int j = 0; j < 4; j++) acc[i][j] += av[i] * bw[j];
        }
        __syncthreads();
    }

    half* Out = g_Wch + ((size_t)b * CC + mbase) * CC + nbase;
#pragma unroll
    for (int i = 0; i < 4; i++) {
        *(__half2*)&Out[(ty * 4 + i) * CC + tx * 4]     = __floats2half2_rn(acc[i][0], acc[i][1]);
        *(__half2*)&Out[(ty * 4 + i) * CC + tx * 4 + 2] = __floats2half2_rn(acc[i][2], acc[i][3]);
    }
}

// ---------------------------------------------------------------------------
// Kernel 5: out[b] = Wc[b] @ q_s[b] / 64 + bo.  grid (32, 2, 8), dyn smem
// ---------------------------------------------------------------------------
__global__ __launch_bounds__(256, 2) void gemm_out(const float* __restrict__ bo,
                                                   float* __restrict__ out)
{
    extern __shared__ __align__(16) char dyn[];
    SmP<true>* s = reinterpret_cast<SmP<true>*>(dyn);

    const int b = blockIdx.z;
    const int mbase = blockIdx.y * 128;
    const int nbase = blockIdx.x * 128;

    float acc[4][4][4] = {};
    gemm_run<true>(s, g_Wch + (size_t)b * CC * CC + mbase * CC, CC,
                   g_Qh + (size_t)b * CC * NN + nbase, NN, CC / 32, acc);

    constexpr float IS = 1.f / 64.f;
    float* OutB = out + ((size_t)b * CC + mbase) * NN + nbase;
    const int lane = threadIdx.x & 31, warp = threadIdx.x >> 5;
    const int wm = (warp >> 2) * 64, wn = (warp & 3) * 32;
    const int g = lane >> 2, tg = lane & 3;
#pragma unroll
    for (int i = 0; i < 4; i++) {
        const int r0 = wm + 16 * i + g;
        const float b0v = bo[mbase + r0], b1v = bo[mbase + r0 + 8];
#pragma unroll
        for (int j = 0; j < 4; j++) {
            const int col = wn + 8 * j + 2 * tg;
            *(float2*)&OutB[(size_t)r0 * NN + col] =
                make_float2(acc[i][j][0] * IS + b0v, acc[i][j][1] * IS + b0v);
            *(float2*)&OutB[(size_t)(r0 + 8) * NN + col] =
                make_float2(acc[i][j][2] * IS + b1v, acc[i][j][3] * IS + b1v);
        }
    }
}

// ---------------------------------------------------------------------------
extern "C" void kernel_launch(void* const* d_in, const int* in_sizes, int n_in,
                              void* d_out, int out_size)
{
    const float* x    = (const float*)d_in[0];
    const float* cp   = (const float*)d_in[1];
    const float* wq   = (const float*)d_in[2];
    const float* bq   = (const float*)d_in[3];
    const float* wkv  = (const float*)d_in[4];
    const float* bkv  = (const float*)d_in[5];
    const float* wo   = (const float*)d_in[6];
    const float* bo   = (const float*)d_in[7];
    float* out = (float*)d_out;

    const int smA = (int)sizeof(SmP<true>);   // ~56.8 KB
    const int smC = (int)sizeof(SmP<false>);  // ~61.4 KB
    cudaFuncSetAttribute(gemm_qkv, cudaFuncAttributeMaxDynamicSharedMemorySize, smA);
    cudaFuncSetAttribute(gemm_ctx, cudaFuncAttributeMaxDynamicSharedMemorySize, smC);
    cudaFuncSetAttribute(gemm_out, cudaFuncAttributeMaxDynamicSharedMemorySize, smA);

    conv_all<<<8288, 256>>>(x, cp, wq, wkv);
    gemm_qkv<<<dim3(32, 6, 8), 256, smA>>>(bq, bkv);
    softmax_all<<<2560, 256>>>();
    gemm_ctx<<<dim3(2, 2, 64), 256, smC>>>();
    gemm_wc<<<dim3(4, 4, 8), 256>>>(wo);
    gemm_out<<<dim3(32, 2, 8), 256, smA>>>(bo, out);
}